// round 17
// baseline (speedup 1.0000x reference)
#include <cuda_runtime.h>
#include <cuda_fp16.h>
#include <math.h>

#define B_SZ   32
#define D_IN   2
#define L_SEQ  4096
#define H_DIM  128
#define NL     6
#define NC     32
#define D_OUT  2
#define NSEQ   (B_SZ * H_DIM)        // 4096
#define TT     64                    // chunk length
#define NCH    (L_SEQ / TT)          // 64 chunks per seq

typedef unsigned long long u64;
typedef unsigned int u32;

// ---------------- tensor-core helpers (baseline sm_103 ISA) ----------------
__device__ __forceinline__ unsigned smaddr(const void* p) {
    unsigned a;
    asm("{ .reg .u64 t; cvta.to.shared.u64 t, %1; cvt.u32.u64 %0, t; }" : "=r"(a) : "l"(p));
    return a;
}
__device__ __forceinline__ void ldm_x4(u32& r0, u32& r1, u32& r2, u32& r3, unsigned addr) {
    asm volatile("ldmatrix.sync.aligned.m8n8.x4.shared.b16 {%0,%1,%2,%3}, [%4];"
                 : "=r"(r0), "=r"(r1), "=r"(r2), "=r"(r3) : "r"(addr));
}
__device__ __forceinline__ void mma_f16(float* c, u32 a0, u32 a1, u32 a2, u32 a3,
                                        u32 b0, u32 b1) {
    asm volatile(
        "mma.sync.aligned.m16n8k16.row.col.f32.f16.f16.f32 "
        "{%0,%1,%2,%3}, {%4,%5,%6,%7}, {%8,%9}, {%0,%1,%2,%3};"
        : "+f"(c[0]), "+f"(c[1]), "+f"(c[2]), "+f"(c[3])
        : "r"(a0), "r"(a1), "r"(a2), "r"(a3), "r"(b0), "r"(b1));
}

// ---------------- glu smem layout (pitch 272B -> conflict-free ldmatrix) -------
#define WPITCH 272
#define SM_W   0                    // 256 x 272 = 69632 (Wf16; zAG overlay)
#define SM_A   69632                // 64 x 272 = 17408 (y fp16)
#define SM_MV  87040                // 64 x float2
#define SMEM_MMA 87552
#define ZPITCH 132
#define GLT 64
#define TILES_PER_BLK 4

// ---------------- ssm_tc smem layout (bytes); MP=144 (16B-divisible) ----------
#define MP   144                    // fp16 row pitch bytes (64 halfs + pad)
#define EPF  68                     // fp32 row pitch in floats
#define SK_HI 0
#define SK_LO 9216
#define SMM_HI 18432
#define SMM_LO 27648
#define SP_HI 36864
#define SP_LO 46080
#define SU_HI 55296
#define SS0   64512
#define SE    73728                 // fp32 E, later Y: 64*68*4 = 17408
#define SUF   91136                 // fp32 u: 17408
#define SMEM_TC 108544

// ---------------- scratch ----------------
__device__ float  g_h[NSEQ * L_SEQ];
__device__ float  g_y[NSEQ * L_SEQ];
__device__ float  g_par[NL * 6 * H_DIM * NC];       // slot4/5 = w^64 re/im
__device__ __half g_Wf[NL * 2 * H_DIM * H_DIM];
__device__ __half g_Khi[NL * H_DIM * 4096], g_Klo[NL * H_DIM * 4096];
__device__ __half g_Mhi[NL * H_DIM * 4096], g_Mlo[NL * H_DIM * 4096];
__device__ __half g_Phi[NL * H_DIM * 4096], g_Plo[NL * H_DIM * 4096];
__device__ float  g_pooled[NSEQ];

// ---------------- param (w^64 for scan; double) ----------------
__global__ void param_kernel(const float* __restrict__ log_dt,
                             const float* __restrict__ log_A_real,
                             const float* __restrict__ A_imag) {
    int t = blockIdx.x * blockDim.x + threadIdx.x;
    if (t >= NL * H_DIM * NC) return;
    int layer = t / (H_DIM * NC);
    int hn    = t % (H_DIM * NC);
    int h     = hn / NC;

    double dt  = exp((double)log_dt[layer * H_DIM + h]);
    double Are = -exp((double)log_A_real[t]);
    double Aim = (double)A_imag[t];
    double xre = Are * dt, xim = Aim * dt;

    double pre = exp(xre * (double)TT);
    double ps, pc;
    sincos(xim * (double)TT, &ps, &pc);

    int S = H_DIM * NC;
    int base = layer * 6 * S + hn;
    g_par[base + 4 * S] = (float)(pre * pc);
    g_par[base + 5 * S] = (float)(pre * ps);
}

// ---------------- matrix gen (double; hi/lo fp16 split) ----------------
__device__ __forceinline__ void wr16(__half* hi, __half* lo, int off, double v) {
    float f = (float)v;
    __half hh = __float2half_rn(f);
    hi[off] = hh;
    lo[off] = __float2half_rn((float)(v - (double)__half2float(hh)));
}

__global__ void matgen_kernel(const float* __restrict__ log_dt,
                              const float* __restrict__ C_re,
                              const float* __restrict__ C_im,
                              const float* __restrict__ log_A_real,
                              const float* __restrict__ A_imag) {
    int lh = blockIdx.x;            // layer*128 + h
    int layer = lh >> 7, h = lh & 127;
    int i = threadIdx.x;            // 0..63
    __shared__ double Ksm[64];

    double dt = exp((double)log_dt[layer * H_DIM + h]);
    double Kacc = 0.0;
    int base = lh * 4096;

    for (int n = 0; n < NC; n++) {
        int idx = (layer * H_DIM + h) * NC + n;
        double Are = -exp((double)log_A_real[idx]);
        double Aim = (double)A_imag[idx];
        double xre = Are * dt, xim = Aim * dt;
        double ex = exp(xre), sy, cy;
        sincos(xim, &sy, &cy);
        double wre = ex * cy, wim = ex * sy;
        double den = Are * Are + Aim * Aim;
        double fre = ((ex * cy - 1.0) * Are + ex * sy * Aim) / den;
        double fim = (ex * sy * Are - (ex * cy - 1.0) * Aim) / den;
        double cre = (double)C_re[idx], cim = (double)C_im[idx];
        double c2re = 2.0 * (cre * fre - cim * fim);
        double c2im = 2.0 * (cre * fim + cim * fre);

        double lr = 0.5 * log(wre * wre + wim * wim);
        double th = atan2(wim, wre);

        // K[i] contribution: Re(c2 * w^i)
        double sk, ck, rk = exp(lr * i);
        sincos(th * i, &sk, &ck);
        Kacc += c2re * (rk * ck) - c2im * (rk * sk);

        // M column i: w^{63-i}
        double sm_, cm_, rm = exp(lr * (63 - i));
        sincos(th * (63 - i), &sm_, &cm_);
        wr16(g_Mhi, g_Mlo, base + (2 * n) * 64 + i, rm * cm_);
        wr16(g_Mhi, g_Mlo, base + (2 * n + 1) * 64 + i, rm * sm_);

        // P row i: Re / -Im of c2 * w^{i+1}
        double sp_, cp_, rp = exp(lr * (i + 1));
        sincos(th * (i + 1), &sp_, &cp_);
        double pwx = rp * cp_, pwy = rp * sp_;
        wr16(g_Phi, g_Plo, base + i * 64 + 2 * n, c2re * pwx - c2im * pwy);
        wr16(g_Phi, g_Plo, base + i * 64 + 2 * n + 1, -(c2re * pwy + c2im * pwx));
    }
    Ksm[i] = Kacc;
    __syncthreads();
    for (int j = 0; j < 64; j++) {
        double v = (j <= i) ? Ksm[i - j] : 0.0;
        wr16(g_Khi, g_Klo, base + i * 64 + j, v);
    }
}

// ---------------- weight fp16 convert ----------------
__global__ void wsplit_kernel(const float* __restrict__ out_W) {
    int t = blockIdx.x * blockDim.x + threadIdx.x;
    if (t >= NL * 2 * H_DIM * H_DIM) return;
    g_Wf[t] = __float2half_rn(out_W[t]);
}

// ---------------- encoder ----------------
__global__ void enc_kernel(const float* __restrict__ x,
                           const float* __restrict__ enc_W,
                           const float* __restrict__ enc_b) {
    int t = blockIdx.x * blockDim.x + threadIdx.x;
    if (t >= NSEQ * (L_SEQ / 4)) return;
    int l4  = t % (L_SEQ / 4);
    int seq = t / (L_SEQ / 4);
    int b = seq / H_DIM;
    int h = seq % H_DIM;
    float w0 = enc_W[h];
    float w1 = enc_W[H_DIM + h];
    float bb = enc_b[h];
    float4 a = ((const float4*)(x + (b * D_IN + 0) * L_SEQ))[l4];
    float4 c = ((const float4*)(x + (b * D_IN + 1) * L_SEQ))[l4];
    float4 r;
    r.x = fmaf(w1, c.x, fmaf(w0, a.x, bb));
    r.y = fmaf(w1, c.y, fmaf(w0, a.y, bb));
    r.z = fmaf(w1, c.z, fmaf(w0, a.z, bb));
    r.w = fmaf(w1, c.w, fmaf(w0, a.w, bb));
    ((float4*)(g_h + seq * L_SEQ))[l4] = r;
}

// ======== tensor-core SSM: E=M@u, fp32 scan, Y=Ktri@u+P@s0, gelu ========
__global__ void __launch_bounds__(256, 2) ssm_tc_kernel(int layer,
                                            const float* __restrict__ Dvec) {
    extern __shared__ char sm[];
    unsigned sb = smaddr(sm);
    int tid = threadIdx.x, w = tid >> 5, lane = tid & 31;
    int h = blockIdx.x >> 5;
    int b = blockIdx.x & 31;
    int seq = b * H_DIM + h;

    // ---- stage 6 matrices (each 64 rows x 128B data, pitch 144) ----
    {
        int mb = (layer * H_DIM + h) * 512;     // uint4 units
        const uint4* s0p = (const uint4*)g_Khi + mb;
        const uint4* s1p = (const uint4*)g_Klo + mb;
        const uint4* s2p = (const uint4*)g_Mhi + mb;
        const uint4* s3p = (const uint4*)g_Mlo + mb;
        const uint4* s4p = (const uint4*)g_Phi + mb;
        const uint4* s5p = (const uint4*)g_Plo + mb;
#pragma unroll
        for (int it = 0; it < 2; it++) {
            int idx = tid + it * 256;
            int row = idx >> 3, c = idx & 7;
            int dst = row * MP + c * 16;
            *(uint4*)(sm + SK_HI + dst)  = __ldg(s0p + idx);
            *(uint4*)(sm + SK_LO + dst)  = __ldg(s1p + idx);
            *(uint4*)(sm + SMM_HI + dst) = __ldg(s2p + idx);
            *(uint4*)(sm + SMM_LO + dst) = __ldg(s3p + idx);
            *(uint4*)(sm + SP_HI + dst)  = __ldg(s4p + idx);
            *(uint4*)(sm + SP_LO + dst)  = __ldg(s5p + idx);
        }
    }
    // ---- stage u (fp32 [c][j] pitch 68; fp16 [c][j] pitch 144) ----
    {
        const float4* src = (const float4*)(g_h + seq * L_SEQ);
#pragma unroll
        for (int it = 0; it < 4; it++) {
            int i4 = tid + it * 256;
            float4 v = __ldg(src + i4);
            int l = i4 * 4;
            int c = l >> 6, j = l & 63;
            *(float4*)(sm + SUF + (c * EPF + j) * 4) = v;
            __half2 p0 = __halves2half2(__float2half_rn(v.x), __float2half_rn(v.y));
            __half2 p1 = __halves2half2(__float2half_rn(v.z), __float2half_rn(v.w));
            *(u32*)(sm + SU_HI + c * MP + j * 2)     = *(u32*)&p0;
            *(u32*)(sm + SU_HI + c * MP + j * 2 + 4) = *(u32*)&p1;
        }
    }
    __syncthreads();

    int ms  = w & 3;
    int nb2 = (w >> 2) * 32;
    int sel = lane >> 3;
    int arow  = ms * 16 + (lane & 7) + (sel & 1) * 8;
    int akadd = (sel >> 1) * 8;
    int brow0 = (lane & 7) + (sel >> 1) * 8;
    int bkadd = (sel & 1) * 8;

    // ---- E = (Mhi + Mlo) @ uhi ----
    {
        float ea[4][4];
#pragma unroll
        for (int n = 0; n < 4; n++)
#pragma unroll
            for (int j = 0; j < 4; j++) ea[n][j] = 0.f;
#pragma unroll
        for (int ks = 0; ks < 4; ks++) {
            u32 bf[2][4];
#pragma unroll
            for (int g = 0; g < 2; g++) {
                int nrow = nb2 + g * 16 + brow0;
                ldm_x4(bf[g][0], bf[g][1], bf[g][2], bf[g][3],
                       sb + SU_HI + nrow * MP + (ks * 16 + bkadd) * 2);
            }
            u32 a0, a1, a2, a3;
            ldm_x4(a0, a1, a2, a3, sb + SMM_HI + arow * MP + (ks * 16 + akadd) * 2);
#pragma unroll
            for (int g = 0; g < 2; g++) {
                mma_f16(ea[2 * g],     a0, a1, a2, a3, bf[g][0], bf[g][1]);
                mma_f16(ea[2 * g + 1], a0, a1, a2, a3, bf[g][2], bf[g][3]);
            }
            ldm_x4(a0, a1, a2, a3, sb + SMM_LO + arow * MP + (ks * 16 + akadd) * 2);
#pragma unroll
            for (int g = 0; g < 2; g++) {
                mma_f16(ea[2 * g],     a0, a1, a2, a3, bf[g][0], bf[g][1]);
                mma_f16(ea[2 * g + 1], a0, a1, a2, a3, bf[g][2], bf[g][3]);
            }
        }
        // scatter E [staterow][chunk]
        float* Ep = (float*)(sm + SE);
        int lrow = ms * 16 + (lane >> 2);
        int ncol = 2 * (lane & 3);
#pragma unroll
        for (int nt = 0; nt < 4; nt++) {
            int n = nb2 + nt * 8 + ncol;
            *(float2*)&Ep[lrow * EPF + n]       = make_float2(ea[nt][0], ea[nt][1]);
            *(float2*)&Ep[(lrow + 8) * EPF + n] = make_float2(ea[nt][2], ea[nt][3]);
        }
    }
    __syncthreads();

    // ---- fp32 scan: s0_{c+1} = w64 * s0_c + E_c  (thread = mode) ----
    if (tid < NC) {
        int n = tid;
        int S = H_DIM * NC;
        const float* par = g_par + layer * 6 * S;
        float are = par[4 * S + h * NC + n];
        float aim = par[5 * S + h * NC + n];
        float sre = 0.f, sim = 0.f;
        *(u32*)(sm + SS0 + 0 * MP + n * 4) = 0u;   // s0 for chunk 0 = 0
        const float* Ep = (float*)(sm + SE);
        for (int c = 0; c < NCH - 1; c++) {
            float er = Ep[(2 * n) * EPF + c];
            float ei = Ep[(2 * n + 1) * EPF + c];
            float nr = fmaf(are, sre, fmaf(-aim, sim, er));
            float ni = fmaf(are, sim, fmaf(aim, sre, ei));
            sre = nr; sim = ni;
            __half2 p = __halves2half2(__float2half_rn(nr), __float2half_rn(ni));
            *(u32*)(sm + SS0 + (c + 1) * MP + n * 4) = *(u32*)&p;
        }
    }
    __syncthreads();

    // ---- Y = (Khi+Klo)@uhi (tri-skip) + (Phi+Plo)@s0 ----
    float ya[4][4];
#pragma unroll
    for (int n = 0; n < 4; n++)
#pragma unroll
        for (int j = 0; j < 4; j++) ya[n][j] = 0.f;

    for (int ks = 0; ks <= ms; ks++) {             // triangular: ks <= m-strip
        u32 bf[2][4];
#pragma unroll
        for (int g = 0; g < 2; g++) {
            int nrow = nb2 + g * 16 + brow0;
            ldm_x4(bf[g][0], bf[g][1], bf[g][2], bf[g][3],
                   sb + SU_HI + nrow * MP + (ks * 16 + bkadd) * 2);
        }
        u32 a0, a1, a2, a3;
        ldm_x4(a0, a1, a2, a3, sb + SK_HI + arow * MP + (ks * 16 + akadd) * 2);
#pragma unroll
        for (int g = 0; g < 2; g++) {
            mma_f16(ya[2 * g],     a0, a1, a2, a3, bf[g][0], bf[g][1]);
            mma_f16(ya[2 * g + 1], a0, a1, a2, a3, bf[g][2], bf[g][3]);
        }
        ldm_x4(a0, a1, a2, a3, sb + SK_LO + arow * MP + (ks * 16 + akadd) * 2);
#pragma unroll
        for (int g = 0; g < 2; g++) {
            mma_f16(ya[2 * g],     a0, a1, a2, a3, bf[g][0], bf[g][1]);
            mma_f16(ya[2 * g + 1], a0, a1, a2, a3, bf[g][2], bf[g][3]);
        }
    }
#pragma unroll
    for (int ks = 0; ks < 4; ks++) {
        u32 bf[2][4];
#pragma unroll
        for (int g = 0; g < 2; g++) {
            int nrow = nb2 + g * 16 + brow0;
            ldm_x4(bf[g][0], bf[g][1], bf[g][2], bf[g][3],
                   sb + SS0 + nrow * MP + (ks * 16 + bkadd) * 2);
        }
        u32 a0, a1, a2, a3;
        ldm_x4(a0, a1, a2, a3, sb + SP_HI + arow * MP + (ks * 16 + akadd) * 2);
#pragma unroll
        for (int g = 0; g < 2; g++) {
            mma_f16(ya[2 * g],     a0, a1, a2, a3, bf[g][0], bf[g][1]);
            mma_f16(ya[2 * g + 1], a0, a1, a2, a3, bf[g][2], bf[g][3]);
        }
        ldm_x4(a0, a1, a2, a3, sb + SP_LO + arow * MP + (ks * 16 + akadd) * 2);
#pragma unroll
        for (int g = 0; g < 2; g++) {
            mma_f16(ya[2 * g],     a0, a1, a2, a3, bf[g][0], bf[g][1]);
            mma_f16(ya[2 * g + 1], a0, a1, a2, a3, bf[g][2], bf[g][3]);
        }
    }

    // scatter Y [i][chunk] onto E region
    {
        float* Yp = (float*)(sm + SE);
        int lrow = ms * 16 + (lane >> 2);
        int ncol = 2 * (lane & 3);
#pragma unroll
        for (int nt = 0; nt < 4; nt++) {
            int n = nb2 + nt * 8 + ncol;
            *(float2*)&Yp[lrow * EPF + n]       = make_float2(ya[nt][0], ya[nt][1]);
            *(float2*)&Yp[(lrow + 8) * EPF + n] = make_float2(ya[nt][2], ya[nt][3]);
        }
    }
    __syncthreads();

    // ---- epilogue: y = Y + D*u, gelu -> g_y ----
    {
        float Dh = Dvec[layer * H_DIM + h];
        int c = tid >> 2, q = tid & 3;
        const float* Yp = (const float*)(sm + SE);
        const float* Up = (const float*)(sm + SUF);
        float out[16];
#pragma unroll
        for (int k = 0; k < 16; k++) {
            int i = q * 16 + k;
            float yv = fmaf(Dh, Up[c * EPF + i], Yp[i * EPF + c]);
            out[k] = 0.5f * yv * (1.f + erff(yv * 0.7071067811865476f));
        }
        float4* dst = (float4*)(g_y + seq * L_SEQ + c * 64 + q * 16);
#pragma unroll
        for (int k = 0; k < 4; k++) dst[k] = ((float4*)out)[k];
    }
}

// ====== GLU via mma.sync fp16 single pass + fused GLU/residual/LN (R15) ======
__global__ void __launch_bounds__(256, 2) glu_mma_kernel(int layer,
                           const float* __restrict__ out_b,
                           const float* __restrict__ ln_g,
                           const float* __restrict__ ln_b) {
    extern __shared__ char smem[];
    unsigned sb = smaddr(smem);
    int tid = threadIdx.x;
    int w = tid >> 5, lane = tid & 31;

    int b   = blockIdx.x >> 4;
    int seg = blockIdx.x & 15;

    int mbase = (w & 3) * 16;
    int nbase = (w >> 2) * 128;
    int sel   = lane >> 3;
    int arow  = mbase + (lane & 7) + (sel & 1) * 8;
    int akadd = (sel >> 1) * 8;
    int brow0 = (lane & 7) + (sel >> 1) * 8;
    int bkadd = (sel & 1) * 8;

    const uint4* wf_g = (const uint4*)(g_Wf + layer * 2 * H_DIM * H_DIM);

    for (int tl = 0; tl < TILES_PER_BLK; tl++) {
        int l0 = seg * 256 + tl * 64;
        __syncthreads();

#pragma unroll
        for (int it = 0; it < 16; it++) {
            int idx = tid + it * 256;
            int o = idx >> 4, c = idx & 15;
            *(uint4*)(smem + SM_W + o * WPITCH + c * 16) = __ldg(wf_g + idx);
        }
#pragma unroll
        for (int it = 0; it < 16; it++) {
            int idx = tid + it * 256;
            int l = idx & 63, kp = idx >> 6;
            const float* r0 = g_y + (b * H_DIM + 2 * kp) * L_SEQ + l0;
            const float* r1 = r0 + L_SEQ;
            float f0 = __ldg(r0 + l);
            float f1 = __ldg(r1 + l);
            __half2 hi2 = __halves2half2(__float2half_rn(f0), __float2half_rn(f1));
            *(u32*)(smem + SM_A + l * WPITCH + kp * 4) = *(u32*)&hi2;
        }
        __syncthreads();

        float acc[16][4];
#pragma unroll
        for (int n = 0; n < 16; n++)
#pragma unroll
            for (int j = 0; j < 4; j++) acc[n][j] = 0.f;

#pragma unroll
        for (int ks = 0; ks < 8; ks++) {
            u32 a0, a1, a2, a3;
            ldm_x4(a0, a1, a2, a3,
                   sb + SM_A + arow * WPITCH + (ks * 16 + akadd) * 2);
#pragma unroll
            for (int nt2 = 0; nt2 < 8; nt2++) {
                u32 b0, b1, b2, b3;
                int nrow = nbase + nt2 * 16 + brow0;
                ldm_x4(b0, b1, b2, b3,
                       sb + SM_W + nrow * WPITCH + (ks * 16 + bkadd) * 2);
                mma_f16(acc[2 * nt2],     a0, a1, a2, a3, b0, b1);
                mma_f16(acc[2 * nt2 + 1], a0, a1, a2, a3, b2, b3);
            }
        }
        __syncthreads();

        {
            float* zbase = (float*)(smem + SM_W) + (w >> 2) * GLT * ZPITCH;
            const float* ob = out_b + layer * 2 * H_DIM + nbase;
            int lrow = mbase + (lane >> 2);
            int ncol = 2 * (lane & 3);
#pragma unroll
            for (int nt = 0; nt < 16; nt++) {
                int n = nt * 8 + ncol;
                float b0 = __ldg(ob + n), b1 = __ldg(ob + n + 1);
                *(float2*)(zbase + lrow * ZPITCH + n) =
                    make_float2(acc[nt][0] + b0, acc[nt][1] + b1);
                *(float2*)(zbase + (lrow + 8) * ZPITCH + n) =
                    make_float2(acc[nt][2] + b0, acc[nt][3] + b1);
            }
        }
        __syncthreads();

        {
            int ch = tid & 127, lh = tid >> 7;
            float* zA = (float*)(smem + SM_W);
            float* zG = zA + GLT * ZPITCH;
            const float* hp = g_h + (b * H_DIM + ch) * L_SEQ + l0 + lh * 32;
            float hv[32];
#pragma unroll
            for (int i = 0; i < 8; i++) ((float4*)hv)[i] = __ldg((const float4*)hp + i);
#pragma unroll
            for (int i = 0; i < 32; i++) {
                int l = lh * 32 + i;
                float a = zA[l * ZPITCH + ch];
                float g = zG[l * ZPITCH + ch];
                zA[l * ZPITCH + ch] = fmaf(a, 1.f / (1.f + expf(-g)), hv[i]);
            }
        }
        __syncthreads();

        {
            float* zA = (float*)(smem + SM_W);
            float2* mv = (float2*)(smem + SM_MV);
#pragma unroll
            for (int l = w; l < GLT; l += 8) {
                float v0 = zA[l * ZPITCH + lane],      v1 = zA[l * ZPITCH + lane + 32];
                float v2 = zA[l * ZPITCH + lane + 64], v3 = zA[l * ZPITCH + lane + 96];
                float s = v0 + v1 + v2 + v3;
                float q = fmaf(v0, v0, fmaf(v1, v1, fmaf(v2, v2, v3 * v3)));
#pragma unroll
                for (int off = 16; off > 0; off >>= 1) {
                    s += __shfl_xor_sync(0xffffffffu, s, off);
                    q += __shfl_xor_sync(0xffffffffu, q, off);
                }
                if (lane == 0) {
                    float m   = s * (1.0f / H_DIM);
                    float var = q * (1.0f / H_DIM) - m * m;
                    mv[l] = make_float2(m, rsqrtf(var + 1e-5f));
                }
            }
        }
        __syncthreads();

        {
            int ch = tid & 127, lh = tid >> 7;
            float* zA = (float*)(smem + SM_W);
            float2* mv = (float2*)(smem + SM_MV);
            float gam = __ldg(ln_g + layer * H_DIM + ch);
            float bet = __ldg(ln_b + layer * H_DIM + ch);
            float r[32];
#pragma unroll
            for (int i = 0; i < 32; i++) {
                int l = lh * 32 + i;
                float2 m = mv[l];
                r[i] = fmaf((zA[l * ZPITCH + ch] - m.x) * m.y, gam, bet);
            }
            float4* wp = (float4*)(g_h + (b * H_DIM + ch) * L_SEQ + l0 + lh * 32);
#pragma unroll
            for (int i = 0; i < 8; i++) wp[i] = ((float4*)r)[i];
        }
    }
}

// ---------------- mean over L ----------------
__global__ void pool_kernel() {
    int seq = blockIdx.x;
    int t   = threadIdx.x;
    const float4* r = (const float4*)(g_h + seq * L_SEQ);
    float s = 0.f;
    for (int i = t; i < L_SEQ / 4; i += 256) {
        float4 v = r[i];
        s += v.x + v.y + v.z + v.w;
    }
    __shared__ float sm[256];
    sm[t] = s;
    __syncthreads();
    for (int off = 128; off > 0; off >>= 1) {
        if (t < off) sm[t] += sm[t + off];
        __syncthreads();
    }
    if (t == 0) g_pooled[seq] = sm[0] * (1.f / L_SEQ);
}

// ---------------- head ----------------
__global__ void head_kernel(const float* __restrict__ head_W,
                            const float* __restrict__ head_b,
                            float* __restrict__ out) {
    int t = threadIdx.x;
    if (t >= B_SZ * D_OUT) return;
    int b = t / D_OUT, o = t % D_OUT;
    float s = head_b[o];
    for (int h = 0; h < H_DIM; h++)
        s = fmaf(g_pooled[b * H_DIM + h], head_W[h * D_OUT + o], s);
    out[t] = s;
}

// ---------------- launch ----------------
extern "C" void kernel_launch(void* const* d_in, const int* in_sizes, int n_in,
                              void* d_out, int out_size) {
    const float* x          = (const float*)d_in[0];
    const float* enc_W      = (const float*)d_in[1];
    const float* enc_b      = (const float*)d_in[2];
    const float* log_dt     = (const float*)d_in[3];
    const float* C_re       = (const float*)d_in[4];
    const float* C_im       = (const float*)d_in[5];
    const float* log_A_real = (const float*)d_in[6];
    const float* A_imag     = (const float*)d_in[7];
    const float* Dvec       = (const float*)d_in[8];
    const float* out_W      = (const float*)d_in[9];
    const float* out_b      = (const float*)d_in[10];
    const float* ln_g       = (const float*)d_in[11];
    const float* ln_b       = (const float*)d_in[12];
    const float* head_W     = (const float*)d_in[13];
    const float* head_b     = (const float*)d_in[14];
    float* out = (float*)d_out;

    cudaFuncSetAttribute(glu_mma_kernel,
                         cudaFuncAttributeMaxDynamicSharedMemorySize, SMEM_MMA);
    cudaFuncSetAttribute(ssm_tc_kernel,
                         cudaFuncAttributeMaxDynamicSharedMemorySize, SMEM_TC);

    param_kernel<<<(NL * H_DIM * NC + 127) / 128, 128>>>(log_dt, log_A_real, A_imag);
    matgen_kernel<<<NL * H_DIM, 64>>>(log_dt, C_re, C_im, log_A_real, A_imag);
    wsplit_kernel<<<(NL * 2 * H_DIM * H_DIM + 255) / 256, 256>>>(out_W);
    enc_kernel<<<(NSEQ * (L_SEQ / 4)) / 256, 256>>>(x, enc_W, enc_b);

    for (int layer = 0; layer < NL; layer++) {
        ssm_tc_kernel<<<H_DIM * B_SZ, 256, SMEM_TC>>>(layer, Dvec);
        glu_mma_kernel<<<B_SZ * 16, 256, SMEM_MMA>>>(layer, out_b, ln_g, ln_b);
    }

    pool_kernel<<<NSEQ, 256>>>();
    head_kernel<<<1, 64>>>(head_W, head_b, out);
}